// round 15
// baseline (speedup 1.0000x reference)
#include <cuda_runtime.h>
#include <cuda_bf16.h>
#include <cuda_fp16.h>
#include <cstdint>

#define N_NODES 100000
#define N_EDGES_MAX 3300000
#define IN_DIM  256
#define OUT_DIM 128
#define ALPHA   0.1f
#define EPS     9e-15f

// ---------------- scratch (device globals; no runtime allocation) ----------
__device__ __align__(16) __half g_h2[(size_t)N_NODES * OUT_DIM];    // fp16 h (25.6 MB)
__device__ __align__(16) float g_score_l[N_NODES];
__device__ __align__(16) float g_score_r[N_NODES];
__device__ __align__(16) __nv_bfloat16 g_wt_hi[OUT_DIM * IN_DIM]; // W^T hi  [n][k]
__device__ __align__(16) __nv_bfloat16 g_wt_lo[OUT_DIM * IN_DIM]; // W^T lo
__device__ int   g_deg[N_NODES];
__device__ int   g_rowptr[N_NODES];
__device__ int   g_cursor[N_NODES];
__device__ __align__(16) int2 g_csr[N_EDGES_MAX];   // packed (dst, w-bits)
__device__ int   g_is64;

__device__ __forceinline__ uint32_t pack2bf16(float x, float y) {
    __nv_bfloat16 hx = __float2bfloat16(x), hy = __float2bfloat16(y);
    uint16_t a = *reinterpret_cast<uint16_t*>(&hx);
    uint16_t b = *reinterpret_cast<uint16_t*>(&hy);
    return (uint32_t)a | ((uint32_t)b << 16);
}
__device__ __forceinline__ uint32_t pack2half(float x, float y) {
    __half2 h = __floats2half2_rn(x, y);
    return *reinterpret_cast<uint32_t*>(&h);
}

// ---------------------------------------------------------------------------
// K1: W^T split into bf16 hi/lo + seed is64 flag
// ---------------------------------------------------------------------------
__global__ __launch_bounds__(256) void prep_w_kernel(const float* __restrict__ W) {
    int i = blockIdx.x * blockDim.x + threadIdx.x;
    if (i == 0) g_is64 = 1;
    if (i >= IN_DIM * OUT_DIM) return;
    int n = i % OUT_DIM;
    int k = i / OUT_DIM;
    float w = W[(size_t)k * OUT_DIM + n];
    __nv_bfloat16 hi = __float2bfloat16(w);
    float lo = w - __bfloat162float(hi);
    g_wt_hi[(size_t)n * IN_DIM + k] = hi;
    g_wt_lo[(size_t)n * IN_DIM + k] = __float2bfloat16(lo);
}

// ---------------------------------------------------------------------------
// K2: zero degree histogram + probe dtype
// ---------------------------------------------------------------------------
__global__ void zero_probe_kernel(const void* ei, int n_elems64) {
    int i = blockIdx.x * blockDim.x + threadIdx.x;
    if (i < N_NODES) g_deg[i] = 0;
    const long long* p = (const long long*)ei;
    int K = n_elems64 < 4096 ? n_elems64 : 4096;
    if (i < K) {
        long long v = p[i];
        if (v < 0 || v >= N_NODES) atomicAnd(&g_is64, 0);
    }
}

// ---------------------------------------------------------------------------
// K3: histogram degrees by src
// ---------------------------------------------------------------------------
__global__ __launch_bounds__(256) void hist_kernel(const void* __restrict__ ei_raw,
                                                   const int n_edges) {
    int i = blockIdx.x * blockDim.x + threadIdx.x;
    if (i >= n_edges) return;
    int src, dst;
    if (g_is64) {
        const long long* ei = (const long long*)ei_raw;
        src = (int)ei[i];
        dst = (int)ei[(size_t)n_edges + i];
    } else {
        const int* ei = (const int*)ei_raw;
        src = ei[i];
        dst = ei[(size_t)n_edges + i];
    }
    if ((unsigned)src < N_NODES && (unsigned)dst < N_NODES)
        atomicAdd(&g_deg[src], 1);
}

// ---------------------------------------------------------------------------
// K4 (PROFILED): mma.sync bf16 GEMM with ldmatrix fragment loads
// ---------------------------------------------------------------------------
#define KCHUNK 64
#define ROW_W   72                        // bf16 per padded row (144 B)
#define ROW_B   144
#define TILE_B  (128 * ROW_B)             // 18432 bytes per tile
#define GEMM_SMEM (4 * TILE_B)

__device__ __forceinline__ void mma16816(float* c, const uint32_t* a, const uint32_t* b) {
    asm volatile(
        "mma.sync.aligned.m16n8k16.row.col.f32.bf16.bf16.f32 "
        "{%0,%1,%2,%3}, {%4,%5,%6,%7}, {%8,%9}, {%0,%1,%2,%3};"
        : "+f"(c[0]), "+f"(c[1]), "+f"(c[2]), "+f"(c[3])
        : "r"(a[0]), "r"(a[1]), "r"(a[2]), "r"(a[3]), "r"(b[0]), "r"(b[1]));
}
__device__ __forceinline__ void ldsm_x4(uint32_t& r0, uint32_t& r1, uint32_t& r2, uint32_t& r3,
                                        uint32_t addr) {
    asm volatile("ldmatrix.sync.aligned.m8n8.x4.shared.b16 {%0,%1,%2,%3}, [%4];"
                 : "=r"(r0), "=r"(r1), "=r"(r2), "=r"(r3) : "r"(addr));
}

__global__ __launch_bounds__(256, 2)
void gemm_mma_kernel(const float* __restrict__ X, const float* __restrict__ attn) {
    extern __shared__ __align__(16) char smem_raw[];
    __nv_bfloat16* sAh = (__nv_bfloat16*)(smem_raw);
    __nv_bfloat16* sAl = (__nv_bfloat16*)(smem_raw + TILE_B);
    __nv_bfloat16* sBh = (__nv_bfloat16*)(smem_raw + 2 * TILE_B);
    __nv_bfloat16* sBl = (__nv_bfloat16*)(smem_raw + 3 * TILE_B);
    float* s_scl = (float*)(smem_raw);            // reused after mainloop
    float* s_scr = (float*)(smem_raw) + 128;

    const int tid  = threadIdx.x;
    const int wid  = tid >> 5;
    const int lane = tid & 31;
    const int g    = lane >> 2;
    const int t    = lane & 3;
    const int wm   = wid >> 2;
    const int wn   = wid & 3;
    const int block_row = blockIdx.x * 128;

    // shared-space byte addresses for ldmatrix
    uint32_t smem_base;
    {
        uint64_t tmp = __cvta_generic_to_shared(smem_raw);
        smem_base = (uint32_t)tmp;
    }
    // A lane offset: row (l&15), col-half (l>>4)*8 elems
    const uint32_t aLane = (uint32_t)((lane & 15) * ROW_B + (lane >> 4) * 16);
    const uint32_t aBase0 = smem_base + (uint32_t)(wm * 64 * ROW_B) + aLane;          // into sAh
    // B lane offset: n row (l&7), nt-pair (l>>4)*8 rows, k-half ((l>>3)&1)*8 elems
    const uint32_t bLane = (uint32_t)((lane & 7) * ROW_B + (lane >> 4) * 8 * ROW_B +
                                      ((lane >> 3) & 1) * 16);
    const uint32_t bBase0 = smem_base + 2 * TILE_B + (uint32_t)(wn * 32 * ROW_B) + bLane; // into sBh

    float acc[4][4][4];
    #pragma unroll
    for (int i = 0; i < 4; i++)
        #pragma unroll
        for (int j = 0; j < 4; j++)
            #pragma unroll
            for (int r = 0; r < 4; r++) acc[i][j][r] = 0.f;

    for (int kc = 0; kc < IN_DIM / KCHUNK; kc++) {
        #pragma unroll
        for (int u = 0; u < 4; u++) {
            const int unit = tid + 256 * u;
            const int row  = unit >> 3;
            const int c8   = (unit & 7) * 8;
            const int gr   = block_row + row;
            float4 v0 = make_float4(0.f, 0.f, 0.f, 0.f);
            float4 v1 = make_float4(0.f, 0.f, 0.f, 0.f);
            if (gr < N_NODES) {
                const float* xp = X + (size_t)gr * IN_DIM + kc * KCHUNK + c8;
                v0 = *(const float4*)(xp);
                v1 = *(const float4*)(xp + 4);
            }
            uint4 hi, lo;
            {
                __nv_bfloat16 h0 = __float2bfloat16(v0.x), h1 = __float2bfloat16(v0.y);
                __nv_bfloat16 h2 = __float2bfloat16(v0.z), h3 = __float2bfloat16(v0.w);
                __nv_bfloat16 h4 = __float2bfloat16(v1.x), h5 = __float2bfloat16(v1.y);
                __nv_bfloat16 h6 = __float2bfloat16(v1.z), h7 = __float2bfloat16(v1.w);
                hi.x = ((uint32_t)*(uint16_t*)&h0) | ((uint32_t)*(uint16_t*)&h1 << 16);
                hi.y = ((uint32_t)*(uint16_t*)&h2) | ((uint32_t)*(uint16_t*)&h3 << 16);
                hi.z = ((uint32_t)*(uint16_t*)&h4) | ((uint32_t)*(uint16_t*)&h5 << 16);
                hi.w = ((uint32_t)*(uint16_t*)&h6) | ((uint32_t)*(uint16_t*)&h7 << 16);
                lo.x = pack2bf16(v0.x - __bfloat162float(h0), v0.y - __bfloat162float(h1));
                lo.y = pack2bf16(v0.z - __bfloat162float(h2), v0.w - __bfloat162float(h3));
                lo.z = pack2bf16(v1.x - __bfloat162float(h4), v1.y - __bfloat162float(h5));
                lo.w = pack2bf16(v1.z - __bfloat162float(h6), v1.w - __bfloat162float(h7));
            }
            *(uint4*)(sAh + row * ROW_W + c8) = hi;
            *(uint4*)(sAl + row * ROW_W + c8) = lo;
        }
        #pragma unroll
        for (int u = 0; u < 4; u++) {
            const int unit = tid + 256 * u;
            const int n    = unit >> 3;
            const int c8   = (unit & 7) * 8;
            const size_t gofs = (size_t)n * IN_DIM + kc * KCHUNK + c8;
            *(uint4*)(sBh + n * ROW_W + c8) = *(const uint4*)(g_wt_hi + gofs);
            *(uint4*)(sBl + n * ROW_W + c8) = *(const uint4*)(g_wt_lo + gofs);
        }
        __syncthreads();

        // term offsets: Ah=0, Al=TILE_B ; Bh=0, Bl=TILE_B
        #define DO_TERM(aOfs, bOfs)                                                    \
        {                                                                              \
            _Pragma("unroll")                                                          \
            for (int ks = 0; ks < 4; ks++) {                                           \
                uint32_t afr[4][4];                                                    \
                _Pragma("unroll")                                                      \
                for (int mt = 0; mt < 4; mt++)                                         \
                    ldsm_x4(afr[mt][0], afr[mt][1], afr[mt][2], afr[mt][3],            \
                            aBase0 + (aOfs) + (uint32_t)(mt * 16 * ROW_B + ks * 32));  \
                uint32_t bfr[4][2];                                                    \
                _Pragma("unroll")                                                      \
                for (int q = 0; q < 2; q++)                                            \
                    ldsm_x4(bfr[q * 2][0], bfr[q * 2][1], bfr[q * 2 + 1][0],           \
                            bfr[q * 2 + 1][1],                                         \
                            bBase0 + (bOfs) + (uint32_t)(q * 16 * ROW_B + ks * 32));   \
                _Pragma("unroll")                                                      \
                for (int mt = 0; mt < 4; mt++)                                         \
                    _Pragma("unroll")                                                  \
                    for (int nt = 0; nt < 4; nt++)                                     \
                        mma16816(acc[mt][nt], afr[mt], bfr[nt]);                       \
            }                                                                          \
        }

        DO_TERM(0u, 0u);            // Ahi * Bhi
        DO_TERM(0u, TILE_B);        // Ahi * Blo
        DO_TERM(TILE_B, 0u);        // Alo * Bhi
        #undef DO_TERM
        __syncthreads();
    }

    // ---- epilogue A: write fp16 H2
    #pragma unroll
    for (int mt = 0; mt < 4; mt++) {
        const int r0 = block_row + wm * 64 + mt * 16 + g;
        const int r1 = r0 + 8;
        #pragma unroll
        for (int nt = 0; nt < 4; nt++) {
            const int col = wn * 32 + nt * 8 + 2 * t;
            if (r0 < N_NODES)
                *(uint32_t*)(g_h2 + (size_t)r0 * OUT_DIM + col) = pack2half(acc[mt][nt][0], acc[mt][nt][1]);
            if (r1 < N_NODES)
                *(uint32_t*)(g_h2 + (size_t)r1 * OUT_DIM + col) = pack2half(acc[mt][nt][2], acc[mt][nt][3]);
        }
    }

    // ---- epilogue B: fused scores from fp32 accumulators
    if (tid < 256) { s_scl[tid] = 0.f; }
    __syncthreads();

    float al_[8], ar_[8];
    #pragma unroll
    for (int nt = 0; nt < 4; nt++) {
        const int col = wn * 32 + nt * 8 + 2 * t;
        al_[nt * 2]     = attn[col];
        al_[nt * 2 + 1] = attn[col + 1];
        ar_[nt * 2]     = attn[OUT_DIM + col];
        ar_[nt * 2 + 1] = attn[OUT_DIM + col + 1];
    }
    #pragma unroll
    for (int mt = 0; mt < 4; mt++) {
        #pragma unroll
        for (int r = 0; r < 2; r++) {
            float dl = 0.f, dr = 0.f;
            #pragma unroll
            for (int nt = 0; nt < 4; nt++) {
                dl += acc[mt][nt][r * 2] * al_[nt * 2] + acc[mt][nt][r * 2 + 1] * al_[nt * 2 + 1];
                dr += acc[mt][nt][r * 2] * ar_[nt * 2] + acc[mt][nt][r * 2 + 1] * ar_[nt * 2 + 1];
            }
            dl += __shfl_xor_sync(0xffffffff, dl, 1);
            dl += __shfl_xor_sync(0xffffffff, dl, 2);
            dr += __shfl_xor_sync(0xffffffff, dr, 1);
            dr += __shfl_xor_sync(0xffffffff, dr, 2);
            if (t == 0) {
                const int lrow = wm * 64 + mt * 16 + g + r * 8;
                atomicAdd(&s_scl[lrow], dl);
                atomicAdd(&s_scr[lrow], dr);
            }
        }
    }
    __syncthreads();
    if (tid < 128) {
        const int grow = block_row + tid;
        if (grow < N_NODES) {
            g_score_l[grow] = s_scl[tid];
            g_score_r[grow] = s_scr[tid];
        }
    }
}

// ---------------------------------------------------------------------------
// K5: exclusive scan of degrees -> rowptr, cursor
// ---------------------------------------------------------------------------
__global__ __launch_bounds__(1024) void scan_kernel() {
    __shared__ int sh[1024];
    const int t = threadIdx.x;
    const int CHUNK = (N_NODES + 1023) / 1024;
    const int lo = t * CHUNK;
    const int hi = min(lo + CHUNK, N_NODES);

    int s = 0;
    for (int i = lo; i < hi; i++) s += g_deg[i];
    sh[t] = s;
    __syncthreads();
    for (int off = 1; off < 1024; off <<= 1) {
        int v = (t >= off) ? sh[t - off] : 0;
        __syncthreads();
        sh[t] += v;
        __syncthreads();
    }
    int run = sh[t] - s;
    for (int i = lo; i < hi; i++) {
        g_rowptr[i] = run;
        g_cursor[i] = run;
        run += g_deg[i];
    }
}

// ---------------------------------------------------------------------------
// K6: scatter edges into CSR (packed int2, precomputed w)
// ---------------------------------------------------------------------------
__global__ __launch_bounds__(256) void scatter_kernel(const void* __restrict__ ei_raw,
                                                      const int n_edges) {
    int i = blockIdx.x * blockDim.x + threadIdx.x;
    if (i >= n_edges) return;
    int src, dst;
    if (g_is64) {
        const long long* ei = (const long long*)ei_raw;
        src = (int)ei[i];
        dst = (int)ei[(size_t)n_edges + i];
    } else {
        const int* ei = (const int*)ei_raw;
        src = ei[i];
        dst = ei[(size_t)n_edges + i];
    }
    if ((unsigned)src >= N_NODES || (unsigned)dst >= N_NODES) return;

    float s = g_score_l[src] + g_score_r[dst];
    s = (s > 0.f) ? s : ALPHA * s;
    const float w = __expf(s);

    const int pos = atomicAdd(&g_cursor[src], 1);
    g_csr[pos] = make_int2(dst, __float_as_int(w));
}

// ---------------------------------------------------------------------------
// K7: aggregate per node (one warp per node, 8-deep unroll)
// ---------------------------------------------------------------------------
__global__ __launch_bounds__(256) void aggregate_kernel(float* __restrict__ out) {
    const int node = (blockIdx.x * blockDim.x + threadIdx.x) >> 5;
    const int lane = threadIdx.x & 31;
    if (node >= N_NODES) return;

    const int start = g_rowptr[node];
    const int deg   = g_deg[node];
    const int end   = start + deg;

    float4 acc = make_float4(0.f, 0.f, 0.f, 0.f);
    float wsum = 0.f;

    int e = start;
    for (; e + 8 <= end; e += 8) {
        int2 r[8];
        #pragma unroll
        for (int j = 0; j < 8; j++) r[j] = g_csr[e + j];
        uint2 p[8];
        #pragma unroll
        for (int j = 0; j < 8; j++)
            p[j] = *(const uint2*)(g_h2 + (size_t)r[j].x * OUT_DIM + lane * 4);
        #pragma unroll
        for (int j = 0; j < 8; j++) {
            const float w = __int_as_float(r[j].y);
            float2 a = __half22float2(*reinterpret_cast<__half2*>(&p[j].x));
            float2 b = __half22float2(*reinterpret_cast<__half2*>(&p[j].y));
            acc.x += w * a.x; acc.y += w * a.y; acc.z += w * b.x; acc.w += w * b.y;
            wsum  += w;
        }
    }
    for (; e < end; e++) {
        int2 r = g_csr[e];
        const float w = __int_as_float(r.y);
        uint2 p = *(const uint2*)(g_h2 + (size_t)r.x * OUT_DIM + lane * 4);
        float2 a = __half22float2(*reinterpret_cast<__half2*>(&p.x));
        float2 b = __half22float2(*reinterpret_cast<__half2*>(&p.y));
        acc.x += w * a.x; acc.y += w * a.y; acc.z += w * b.x; acc.w += w * b.y;
        wsum  += w;
    }

    const float inv = 1.0f / (wsum + EPS);
    acc.x *= inv; acc.y *= inv; acc.z *= inv; acc.w *= inv;
    acc.x = (acc.x > 0.f) ? acc.x : ALPHA * acc.x;
    acc.y = (acc.y > 0.f) ? acc.y : ALPHA * acc.y;
    acc.z = (acc.z > 0.f) ? acc.z : ALPHA * acc.z;
    acc.w = (acc.w > 0.f) ? acc.w : ALPHA * acc.w;
    *(float4*)(out + (size_t)node * OUT_DIM + lane * 4) = acc;
}

// ---------------------------------------------------------------------------
extern "C" void kernel_launch(void* const* d_in, const int* in_sizes, int n_in,
                              void* d_out, int out_size) {
    const float* x    = (const float*)d_in[0];
    const void*  ei   = d_in[1];
    const float* W    = (const float*)d_in[2];
    const float* attn = (const float*)d_in[3];
    float*       out  = (float*)d_out;

    const int n_edges = in_sizes[1] / 2;

    cudaFuncSetAttribute(gemm_mma_kernel, cudaFuncAttributeMaxDynamicSharedMemorySize, GEMM_SMEM);

    prep_w_kernel<<<(IN_DIM * OUT_DIM + 255) / 256, 256>>>(W);          // 1
    zero_probe_kernel<<<(N_NODES + 255) / 256, 256>>>(ei, in_sizes[1]); // 2
    hist_kernel<<<(n_edges + 255) / 256, 256>>>(ei, n_edges);           // 3
    gemm_mma_kernel<<<(N_NODES + 127) / 128, 256, GEMM_SMEM>>>(x, attn);// 4 <- profiled
    scan_kernel<<<1, 1024>>>();                                          // 5
    scatter_kernel<<<(n_edges + 255) / 256, 256>>>(ei, n_edges);        // 6
    aggregate_kernel<<<(N_NODES * 32 + 255) / 256, 256>>>(out);         // 7
}

// round 16
// speedup vs baseline: 1.0937x; 1.0937x over previous
#include <cuda_runtime.h>
#include <cuda_bf16.h>
#include <cuda_fp16.h>
#include <cstdint>

#define N_NODES 100000
#define N_EDGES_MAX 3300000
#define IN_DIM  256
#define OUT_DIM 128
#define ALPHA   0.1f
#define EPS     9e-15f

// ---------------- scratch (device globals; no runtime allocation) ----------
__device__ __align__(16) __half g_h2[(size_t)N_NODES * OUT_DIM];    // fp16 h (25.6 MB)
__device__ __align__(16) float g_score_l[N_NODES];
__device__ __align__(16) float g_score_r[N_NODES];
__device__ __align__(16) __nv_bfloat16 g_wt_hi[OUT_DIM * IN_DIM]; // W^T hi  [n][k]
__device__ __align__(16) __nv_bfloat16 g_wt_lo[OUT_DIM * IN_DIM]; // W^T lo
__device__ int   g_deg[N_NODES];
__device__ int   g_rowptr[N_NODES];
__device__ int   g_cursor[N_NODES];
__device__ __align__(16) int2 g_csr[N_EDGES_MAX];   // packed (dst, w-bits)
__device__ int   g_is64;

__device__ __forceinline__ uint32_t pack2bf16(float x, float y) {
    __nv_bfloat16 hx = __float2bfloat16(x), hy = __float2bfloat16(y);
    uint16_t a = *reinterpret_cast<uint16_t*>(&hx);
    uint16_t b = *reinterpret_cast<uint16_t*>(&hy);
    return (uint32_t)a | ((uint32_t)b << 16);
}
__device__ __forceinline__ uint32_t pack2half(float x, float y) {
    __half2 h = __floats2half2_rn(x, y);
    return *reinterpret_cast<uint32_t*>(&h);
}

// ---------------------------------------------------------------------------
// K1: W^T split into bf16 hi/lo + seed is64 flag
// ---------------------------------------------------------------------------
__global__ __launch_bounds__(256) void prep_w_kernel(const float* __restrict__ W) {
    int i = blockIdx.x * blockDim.x + threadIdx.x;
    if (i == 0) g_is64 = 1;
    if (i >= IN_DIM * OUT_DIM) return;
    int n = i % OUT_DIM;
    int k = i / OUT_DIM;
    float w = W[(size_t)k * OUT_DIM + n];
    __nv_bfloat16 hi = __float2bfloat16(w);
    float lo = w - __bfloat162float(hi);
    g_wt_hi[(size_t)n * IN_DIM + k] = hi;
    g_wt_lo[(size_t)n * IN_DIM + k] = __float2bfloat16(lo);
}

// ---------------------------------------------------------------------------
// K2: zero degree histogram + probe dtype
// ---------------------------------------------------------------------------
__global__ void zero_probe_kernel(const void* ei, int n_elems64) {
    int i = blockIdx.x * blockDim.x + threadIdx.x;
    if (i < N_NODES) g_deg[i] = 0;
    const long long* p = (const long long*)ei;
    int K = n_elems64 < 4096 ? n_elems64 : 4096;
    if (i < K) {
        long long v = p[i];
        if (v < 0 || v >= N_NODES) atomicAnd(&g_is64, 0);
    }
}

// ---------------------------------------------------------------------------
// K3: histogram degrees by src
// ---------------------------------------------------------------------------
__global__ __launch_bounds__(256) void hist_kernel(const void* __restrict__ ei_raw,
                                                   const int n_edges) {
    int i = blockIdx.x * blockDim.x + threadIdx.x;
    if (i >= n_edges) return;
    int src, dst;
    if (g_is64) {
        const long long* ei = (const long long*)ei_raw;
        src = (int)ei[i];
        dst = (int)ei[(size_t)n_edges + i];
    } else {
        const int* ei = (const int*)ei_raw;
        src = ei[i];
        dst = ei[(size_t)n_edges + i];
    }
    if ((unsigned)src < N_NODES && (unsigned)dst < N_NODES)
        atomicAdd(&g_deg[src], 1);
}

// ---------------------------------------------------------------------------
// K4 (PROFILED): mma.sync bf16 GEMM, ldmatrix + fragment reuse across terms
// ---------------------------------------------------------------------------
#define KCHUNK 64
#define ROW_W   72                        // bf16 per padded row (144 B)
#define ROW_B   144
#define TILE_B  (128 * ROW_B)             // 18432 bytes per tile
#define GEMM_SMEM (4 * TILE_B)

__device__ __forceinline__ void mma16816(float* c, const uint32_t* a, const uint32_t* b) {
    asm volatile(
        "mma.sync.aligned.m16n8k16.row.col.f32.bf16.bf16.f32 "
        "{%0,%1,%2,%3}, {%4,%5,%6,%7}, {%8,%9}, {%0,%1,%2,%3};"
        : "+f"(c[0]), "+f"(c[1]), "+f"(c[2]), "+f"(c[3])
        : "r"(a[0]), "r"(a[1]), "r"(a[2]), "r"(a[3]), "r"(b[0]), "r"(b[1]));
}
__device__ __forceinline__ void ldsm_x4(uint32_t& r0, uint32_t& r1, uint32_t& r2, uint32_t& r3,
                                        uint32_t addr) {
    asm volatile("ldmatrix.sync.aligned.m8n8.x4.shared.b16 {%0,%1,%2,%3}, [%4];"
                 : "=r"(r0), "=r"(r1), "=r"(r2), "=r"(r3) : "r"(addr));
}

__global__ __launch_bounds__(256, 2)
void gemm_mma_kernel(const float* __restrict__ X, const float* __restrict__ attn) {
    extern __shared__ __align__(16) char smem_raw[];
    __nv_bfloat16* sAh = (__nv_bfloat16*)(smem_raw);
    __nv_bfloat16* sAl = (__nv_bfloat16*)(smem_raw + TILE_B);
    __nv_bfloat16* sBh = (__nv_bfloat16*)(smem_raw + 2 * TILE_B);
    __nv_bfloat16* sBl = (__nv_bfloat16*)(smem_raw + 3 * TILE_B);
    float* s_scl = (float*)(smem_raw);            // reused after mainloop
    float* s_scr = (float*)(smem_raw) + 128;

    const int tid  = threadIdx.x;
    const int wid  = tid >> 5;
    const int lane = tid & 31;
    const int g    = lane >> 2;
    const int t    = lane & 3;
    const int wm   = wid >> 2;
    const int wn   = wid & 3;
    const int block_row = blockIdx.x * 128;

    uint32_t smem_base;
    {
        uint64_t tmp = __cvta_generic_to_shared(smem_raw);
        smem_base = (uint32_t)tmp;
    }
    const uint32_t aLane = (uint32_t)((lane & 15) * ROW_B + (lane >> 4) * 16);
    const uint32_t aBase0 = smem_base + (uint32_t)(wm * 64 * ROW_B) + aLane;
    const uint32_t bLane = (uint32_t)((lane & 7) * ROW_B + (lane >> 4) * 8 * ROW_B +
                                      ((lane >> 3) & 1) * 16);
    const uint32_t bBase0 = smem_base + 2 * TILE_B + (uint32_t)(wn * 32 * ROW_B) + bLane;

    float acc[4][4][4];
    #pragma unroll
    for (int i = 0; i < 4; i++)
        #pragma unroll
        for (int j = 0; j < 4; j++)
            #pragma unroll
            for (int r = 0; r < 4; r++) acc[i][j][r] = 0.f;

    for (int kc = 0; kc < IN_DIM / KCHUNK; kc++) {
        #pragma unroll
        for (int u = 0; u < 4; u++) {
            const int unit = tid + 256 * u;
            const int row  = unit >> 3;
            const int c8   = (unit & 7) * 8;
            const int gr   = block_row + row;
            float4 v0 = make_float4(0.f, 0.f, 0.f, 0.f);
            float4 v1 = make_float4(0.f, 0.f, 0.f, 0.f);
            if (gr < N_NODES) {
                const float* xp = X + (size_t)gr * IN_DIM + kc * KCHUNK + c8;
                v0 = *(const float4*)(xp);
                v1 = *(const float4*)(xp + 4);
            }
            uint4 hi, lo;
            {
                __nv_bfloat16 h0 = __float2bfloat16(v0.x), h1 = __float2bfloat16(v0.y);
                __nv_bfloat16 h2 = __float2bfloat16(v0.z), h3 = __float2bfloat16(v0.w);
                __nv_bfloat16 h4 = __float2bfloat16(v1.x), h5 = __float2bfloat16(v1.y);
                __nv_bfloat16 h6 = __float2bfloat16(v1.z), h7 = __float2bfloat16(v1.w);
                hi.x = ((uint32_t)*(uint16_t*)&h0) | ((uint32_t)*(uint16_t*)&h1 << 16);
                hi.y = ((uint32_t)*(uint16_t*)&h2) | ((uint32_t)*(uint16_t*)&h3 << 16);
                hi.z = ((uint32_t)*(uint16_t*)&h4) | ((uint32_t)*(uint16_t*)&h5 << 16);
                hi.w = ((uint32_t)*(uint16_t*)&h6) | ((uint32_t)*(uint16_t*)&h7 << 16);
                lo.x = pack2bf16(v0.x - __bfloat162float(h0), v0.y - __bfloat162float(h1));
                lo.y = pack2bf16(v0.z - __bfloat162float(h2), v0.w - __bfloat162float(h3));
                lo.z = pack2bf16(v1.x - __bfloat162float(h4), v1.y - __bfloat162float(h5));
                lo.w = pack2bf16(v1.z - __bfloat162float(h6), v1.w - __bfloat162float(h7));
            }
            *(uint4*)(sAh + row * ROW_W + c8) = hi;
            *(uint4*)(sAl + row * ROW_W + c8) = lo;
        }
        #pragma unroll
        for (int u = 0; u < 4; u++) {
            const int unit = tid + 256 * u;
            const int n    = unit >> 3;
            const int c8   = (unit & 7) * 8;
            const size_t gofs = (size_t)n * IN_DIM + kc * KCHUNK + c8;
            *(uint4*)(sBh + n * ROW_W + c8) = *(const uint4*)(g_wt_hi + gofs);
            *(uint4*)(sBl + n * ROW_W + c8) = *(const uint4*)(g_wt_lo + gofs);
        }
        __syncthreads();

        // fragment-reuse inner loop: per ks load Ahi,Bhi,Alo,Blo once
        #pragma unroll
        for (int ks = 0; ks < 4; ks++) {
            uint32_t ahi[4][4], alo[4][4];
            uint32_t bhi[4][2], blo[4][2];

            #pragma unroll
            for (int mt = 0; mt < 4; mt++)
                ldsm_x4(ahi[mt][0], ahi[mt][1], ahi[mt][2], ahi[mt][3],
                        aBase0 + (uint32_t)(mt * 16 * ROW_B + ks * 32));
            #pragma unroll
            for (int q = 0; q < 2; q++)
                ldsm_x4(bhi[q * 2][0], bhi[q * 2][1], bhi[q * 2 + 1][0], bhi[q * 2 + 1][1],
                        bBase0 + (uint32_t)(q * 16 * ROW_B + ks * 32));

            // term 1: Ahi * Bhi
            #pragma unroll
            for (int mt = 0; mt < 4; mt++)
                #pragma unroll
                for (int nt = 0; nt < 4; nt++)
                    mma16816(acc[mt][nt], ahi[mt], bhi[nt]);

            #pragma unroll
            for (int mt = 0; mt < 4; mt++)
                ldsm_x4(alo[mt][0], alo[mt][1], alo[mt][2], alo[mt][3],
                        aBase0 + TILE_B + (uint32_t)(mt * 16 * ROW_B + ks * 32));

            // term 3: Alo * Bhi
            #pragma unroll
            for (int mt = 0; mt < 4; mt++)
                #pragma unroll
                for (int nt = 0; nt < 4; nt++)
                    mma16816(acc[mt][nt], alo[mt], bhi[nt]);

            #pragma unroll
            for (int q = 0; q < 2; q++)
                ldsm_x4(blo[q * 2][0], blo[q * 2][1], blo[q * 2 + 1][0], blo[q * 2 + 1][1],
                        bBase0 + TILE_B + (uint32_t)(q * 16 * ROW_B + ks * 32));

            // term 2: Ahi * Blo
            #pragma unroll
            for (int mt = 0; mt < 4; mt++)
                #pragma unroll
                for (int nt = 0; nt < 4; nt++)
                    mma16816(acc[mt][nt], ahi[mt], blo[nt]);
        }
        __syncthreads();
    }

    // ---- epilogue A: write fp16 H2
    #pragma unroll
    for (int mt = 0; mt < 4; mt++) {
        const int r0 = block_row + wm * 64 + mt * 16 + g;
        const int r1 = r0 + 8;
        #pragma unroll
        for (int nt = 0; nt < 4; nt++) {
            const int col = wn * 32 + nt * 8 + 2 * t;
            if (r0 < N_NODES)
                *(uint32_t*)(g_h2 + (size_t)r0 * OUT_DIM + col) = pack2half(acc[mt][nt][0], acc[mt][nt][1]);
            if (r1 < N_NODES)
                *(uint32_t*)(g_h2 + (size_t)r1 * OUT_DIM + col) = pack2half(acc[mt][nt][2], acc[mt][nt][3]);
        }
    }

    // ---- epilogue B: fused scores from fp32 accumulators
    if (tid < 256) { s_scl[tid] = 0.f; }
    __syncthreads();

    float al_[8], ar_[8];
    #pragma unroll
    for (int nt = 0; nt < 4; nt++) {
        const int col = wn * 32 + nt * 8 + 2 * t;
        al_[nt * 2]     = attn[col];
        al_[nt * 2 + 1] = attn[col + 1];
        ar_[nt * 2]     = attn[OUT_DIM + col];
        ar_[nt * 2 + 1] = attn[OUT_DIM + col + 1];
    }
    #pragma unroll
    for (int mt = 0; mt < 4; mt++) {
        #pragma unroll
        for (int r = 0; r < 2; r++) {
            float dl = 0.f, dr = 0.f;
            #pragma unroll
            for (int nt = 0; nt < 4; nt++) {
                dl += acc[mt][nt][r * 2] * al_[nt * 2] + acc[mt][nt][r * 2 + 1] * al_[nt * 2 + 1];
                dr += acc[mt][nt][r * 2] * ar_[nt * 2] + acc[mt][nt][r * 2 + 1] * ar_[nt * 2 + 1];
            }
            dl += __shfl_xor_sync(0xffffffff, dl, 1);
            dl += __shfl_xor_sync(0xffffffff, dl, 2);
            dr += __shfl_xor_sync(0xffffffff, dr, 1);
            dr += __shfl_xor_sync(0xffffffff, dr, 2);
            if (t == 0) {
                const int lrow = wm * 64 + mt * 16 + g + r * 8;
                atomicAdd(&s_scl[lrow], dl);
                atomicAdd(&s_scr[lrow], dr);
            }
        }
    }
    __syncthreads();
    if (tid < 128) {
        const int grow = block_row + tid;
        if (grow < N_NODES) {
            g_score_l[grow] = s_scl[tid];
            g_score_r[grow] = s_scr[tid];
        }
    }
}

// ---------------------------------------------------------------------------
// K5: exclusive scan of degrees -> rowptr, cursor
// ---------------------------------------------------------------------------
__global__ __launch_bounds__(1024) void scan_kernel() {
    __shared__ int sh[1024];
    const int t = threadIdx.x;
    const int CHUNK = (N_NODES + 1023) / 1024;
    const int lo = t * CHUNK;
    const int hi = min(lo + CHUNK, N_NODES);

    int s = 0;
    for (int i = lo; i < hi; i++) s += g_deg[i];
    sh[t] = s;
    __syncthreads();
    for (int off = 1; off < 1024; off <<= 1) {
        int v = (t >= off) ? sh[t - off] : 0;
        __syncthreads();
        sh[t] += v;
        __syncthreads();
    }
    int run = sh[t] - s;
    for (int i = lo; i < hi; i++) {
        g_rowptr[i] = run;
        g_cursor[i] = run;
        run += g_deg[i];
    }
}

// ---------------------------------------------------------------------------
// K6: scatter edges into CSR (packed int2, precomputed w)
// ---------------------------------------------------------------------------
__global__ __launch_bounds__(256) void scatter_kernel(const void* __restrict__ ei_raw,
                                                      const int n_edges) {
    int i = blockIdx.x * blockDim.x + threadIdx.x;
    if (i >= n_edges) return;
    int src, dst;
    if (g_is64) {
        const long long* ei = (const long long*)ei_raw;
        src = (int)ei[i];
        dst = (int)ei[(size_t)n_edges + i];
    } else {
        const int* ei = (const int*)ei_raw;
        src = ei[i];
        dst = ei[(size_t)n_edges + i];
    }
    if ((unsigned)src >= N_NODES || (unsigned)dst >= N_NODES) return;

    float s = g_score_l[src] + g_score_r[dst];
    s = (s > 0.f) ? s : ALPHA * s;
    const float w = __expf(s);

    const int pos = atomicAdd(&g_cursor[src], 1);
    g_csr[pos] = make_int2(dst, __float_as_int(w));
}

// ---------------------------------------------------------------------------
// K7: aggregate per node (one warp per node, 8-deep unroll)
// ---------------------------------------------------------------------------
__global__ __launch_bounds__(256) void aggregate_kernel(float* __restrict__ out) {
    const int node = (blockIdx.x * blockDim.x + threadIdx.x) >> 5;
    const int lane = threadIdx.x & 31;
    if (node >= N_NODES) return;

    const int start = g_rowptr[node];
    const int deg   = g_deg[node];
    const int end   = start + deg;

    float4 acc = make_float4(0.f, 0.f, 0.f, 0.f);
    float wsum = 0.f;

    int e = start;
    for (; e + 8 <= end; e += 8) {
        int2 r[8];
        #pragma unroll
        for (int j = 0; j < 8; j++) r[j] = g_csr[e + j];
        uint2 p[8];
        #pragma unroll
        for (int j = 0; j < 8; j++)
            p[j] = *(const uint2*)(g_h2 + (size_t)r[j].x * OUT_DIM + lane * 4);
        #pragma unroll
        for (int j = 0; j < 8; j++) {
            const float w = __int_as_float(r[j].y);
            float2 a = __half22float2(*reinterpret_cast<__half2*>(&p[j].x));
            float2 b = __half22float2(*reinterpret_cast<__half2*>(&p[j].y));
            acc.x += w * a.x; acc.y += w * a.y; acc.z += w * b.x; acc.w += w * b.y;
            wsum  += w;
        }
    }
    for (; e < end; e++) {
        int2 r = g_csr[e];
        const float w = __int_as_float(r.y);
        uint2 p = *(const uint2*)(g_h2 + (size_t)r.x * OUT_DIM + lane * 4);
        float2 a = __half22float2(*reinterpret_cast<__half2*>(&p.x));
        float2 b = __half22float2(*reinterpret_cast<__half2*>(&p.y));
        acc.x += w * a.x; acc.y += w * a.y; acc.z += w * b.x; acc.w += w * b.y;
        wsum  += w;
    }

    const float inv = 1.0f / (wsum + EPS);
    acc.x *= inv; acc.y *= inv; acc.z *= inv; acc.w *= inv;
    acc.x = (acc.x > 0.f) ? acc.x : ALPHA * acc.x;
    acc.y = (acc.y > 0.f) ? acc.y : ALPHA * acc.y;
    acc.z = (acc.z > 0.f) ? acc.z : ALPHA * acc.z;
    acc.w = (acc.w > 0.f) ? acc.w : ALPHA * acc.w;
    *(float4*)(out + (size_t)node * OUT_DIM + lane * 4) = acc;
}

// ---------------------------------------------------------------------------
extern "C" void kernel_launch(void* const* d_in, const int* in_sizes, int n_in,
                              void* d_out, int out_size) {
    const float* x    = (const float*)d_in[0];
    const void*  ei   = d_in[1];
    const float* W    = (const float*)d_in[2];
    const float* attn = (const float*)d_in[3];
    float*       out  = (float*)d_out;

    const int n_edges = in_sizes[1] / 2;

    cudaFuncSetAttribute(gemm_mma_kernel, cudaFuncAttributeMaxDynamicSharedMemorySize, GEMM_SMEM);

    prep_w_kernel<<<(IN_DIM * OUT_DIM + 255) / 256, 256>>>(W);          // 1
    zero_probe_kernel<<<(N_NODES + 255) / 256, 256>>>(ei, in_sizes[1]); // 2
    hist_kernel<<<(n_edges + 255) / 256, 256>>>(ei, n_edges);           // 3
    gemm_mma_kernel<<<(N_NODES + 127) / 128, 256, GEMM_SMEM>>>(x, attn);// 4 <- profiled
    scan_kernel<<<1, 1024>>>();                                          // 5
    scatter_kernel<<<(n_edges + 255) / 256, 256>>>(ei, n_edges);        // 6
    aggregate_kernel<<<(N_NODES * 32 + 255) / 256, 256>>>(out);         // 7
}